// round 1
// baseline (speedup 1.0000x reference)
#include <cuda_runtime.h>
#include <cstdint>

// ---------------------------------------------------------------------------
// GCNNet: 3-layer GCN + log_softmax.
//   per layer: h = in @ W ; agg[i] = h[i]*dinv[i]^2 + b ; agg[d] += h[s]*dinv[s]*dinv[d]
//   relu between layers, log_softmax at the end.
// Shapes: N=100000, E=3200000, din=128, dh=64, dout=6.
// ---------------------------------------------------------------------------

#define MAXN 100000
#define MAXE 3200000

__device__ __align__(16) float g_dinv[MAXN];
__device__ int   g_src[MAXE];
__device__ int   g_dst[MAXE];
__device__ __align__(16) float g_norm[MAXE];
__device__ __align__(16) float g_bufA[(size_t)MAXN * 64];
__device__ __align__(16) float g_bufB[(size_t)MAXN * 64];
__device__ __align__(16) float g_h3[(size_t)MAXN * 8];
__device__ __align__(16) float g_agg3[(size_t)MAXN * 8];
__device__ int   g_is64;

// ---------------- vector global reductions (sm_90+) ----------------
__device__ __forceinline__ void red_add_v4(float* p, float a, float b, float c, float d) {
    asm volatile("red.global.add.v4.f32 [%0], {%1, %2, %3, %4};"
                 :: "l"(p), "f"(a), "f"(b), "f"(c), "f"(d) : "memory");
}
__device__ __forceinline__ void red_add_v2(float* p, float a, float b) {
    asm volatile("red.global.add.v2.f32 [%0], {%1, %2};"
                 :: "l"(p), "f"(a), "f"(b) : "memory");
}

// ---------------- setup ----------------
__global__ void k_detect_dtype(const void* ei, int e, int n) {
    if (blockIdx.x == 0 && threadIdx.x == 0) {
        // If the buffer is really int64, every 8-byte word is in [0, n).
        // If it is int32, the 8-byte interpretation combines two node ids:
        // lo + hi*2^32, which is >= 2^32 unless hi==0 (prob 1e-5 per entry).
        const long long* p = (const long long*)ei;
        int m = e < 1024 ? e : 1024;
        int ok = 1;
        for (int i = 0; i < m; i++) {
            long long v = p[i];
            if (v < 0 || v >= (long long)n) { ok = 0; break; }
        }
        g_is64 = ok;
    }
}

__global__ void k_init_deg(int n) {
    int i = blockIdx.x * blockDim.x + threadIdx.x;
    if (i < n) g_dinv[i] = 1.0f;  // self-loop contributes 1 to the degree
}

__global__ void k_convert_count(const void* ei, int e) {
    int i = blockIdx.x * blockDim.x + threadIdx.x;
    if (i >= e) return;
    int s, d;
    if (g_is64) {
        const long long* p = (const long long*)ei;
        s = (int)p[i];
        d = (int)p[e + i];
    } else {
        const int* p = (const int*)ei;
        s = p[i];
        d = p[e + i];
    }
    g_src[i] = s;
    g_dst[i] = d;
    atomicAdd(&g_dinv[d], 1.0f);
}

__global__ void k_rsqrt(int n) {
    int i = blockIdx.x * blockDim.x + threadIdx.x;
    if (i < n) g_dinv[i] = rsqrtf(g_dinv[i]);
}

__global__ void k_edge_norm(int e) {
    int i = blockIdx.x * blockDim.x + threadIdx.x;
    if (i < e) g_norm[i] = g_dinv[g_src[i]] * g_dinv[g_dst[i]];
}

// ---------------- GEMM: [n, K] @ [K, 64] -> [n, 64] ----------------
// One warp computes 4 rows; W staged in smem; x loaded as float4.
template <int K, bool RELU>
__global__ void k_gemm64(const float* __restrict__ in, const float* __restrict__ W,
                         float* __restrict__ out, int n) {
    __shared__ float Ws[K * 64];
    for (int i = threadIdx.x; i < K * 64; i += blockDim.x) Ws[i] = W[i];
    __syncthreads();

    int warp = (blockIdx.x * blockDim.x + threadIdx.x) >> 5;
    int lane = threadIdx.x & 31;
    int row0 = warp * 4;
    if (row0 >= n) return;
    int rows = n - row0; if (rows > 4) rows = 4;

    float acc[4][2] = {};
    for (int k = 0; k < K; k += 4) {
        float4 xv[4];
#pragma unroll
        for (int r = 0; r < 4; r++) {
            xv[r] = (r < rows) ? *(const float4*)(in + (size_t)(row0 + r) * K + k)
                               : make_float4(0.f, 0.f, 0.f, 0.f);
            if (RELU) {
                xv[r].x = fmaxf(xv[r].x, 0.f); xv[r].y = fmaxf(xv[r].y, 0.f);
                xv[r].z = fmaxf(xv[r].z, 0.f); xv[r].w = fmaxf(xv[r].w, 0.f);
            }
        }
#pragma unroll
        for (int kk = 0; kk < 4; kk++) {
            float w0 = Ws[(k + kk) * 64 + lane];
            float w1 = Ws[(k + kk) * 64 + lane + 32];
#pragma unroll
            for (int r = 0; r < 4; r++) {
                float x = (kk == 0) ? xv[r].x : (kk == 1) ? xv[r].y
                        : (kk == 2) ? xv[r].z : xv[r].w;
                acc[r][0] = fmaf(x, w0, acc[r][0]);
                acc[r][1] = fmaf(x, w1, acc[r][1]);
            }
        }
    }
#pragma unroll
    for (int r = 0; r < 4; r++) {
        if (r < rows) {
            out[(size_t)(row0 + r) * 64 + lane]      = acc[r][0];
            out[(size_t)(row0 + r) * 64 + lane + 32] = acc[r][1];
        }
    }
}

// ---------------- agg init: agg[i] = h[i]*dinv[i]^2 + b ----------------
__global__ void k_init64(const float* __restrict__ h, const float* __restrict__ b,
                         float* __restrict__ agg, int n) {
    int t = blockIdx.x * blockDim.x + threadIdx.x;
    if (t >= n * 16) return;
    int row = t >> 4, c4 = (t & 15) * 4;
    float di = g_dinv[row];
    float w = di * di;
    float4 v = *(const float4*)(h + (size_t)row * 64 + c4);
    float4 bb = *(const float4*)(b + c4);
    float4 o = make_float4(fmaf(v.x, w, bb.x), fmaf(v.y, w, bb.y),
                           fmaf(v.z, w, bb.z), fmaf(v.w, w, bb.w));
    *(float4*)(agg + (size_t)row * 64 + c4) = o;
}

// ---------------- edge scatter, 64-wide: 16 threads per edge ----------------
__global__ void k_scatter64(const float* __restrict__ h, float* __restrict__ agg, int e) {
    int t = blockIdx.x * blockDim.x + threadIdx.x;
    if (t >= e * 16) return;
    int edge = t >> 4, q = (t & 15) * 4;
    int s = g_src[edge], d = g_dst[edge];
    float w = g_norm[edge];
    float4 v = *(const float4*)(h + (size_t)s * 64 + q);
    red_add_v4(agg + (size_t)d * 64 + q, v.x * w, v.y * w, v.z * w, v.w * w);
}

// ---------------- layer 3: [n,64] @ [64,6] -> [n,8] (padded) ----------------
__global__ void k_gemm3(const float* __restrict__ in, const float* __restrict__ W,
                        float* __restrict__ out, int n) {
    __shared__ float Ws[64 * 6];
    for (int i = threadIdx.x; i < 64 * 6; i += blockDim.x) Ws[i] = W[i];
    __syncthreads();
    int row = blockIdx.x * blockDim.x + threadIdx.x;
    if (row >= n) return;
    float acc[6] = {};
    const float* xr = in + (size_t)row * 64;
    for (int k = 0; k < 64; k++) {
        float x = fmaxf(xr[k], 0.f);
#pragma unroll
        for (int j = 0; j < 6; j++) acc[j] = fmaf(x, Ws[k * 6 + j], acc[j]);
    }
    float* o = out + (size_t)row * 8;
#pragma unroll
    for (int j = 0; j < 6; j++) o[j] = acc[j];
    o[6] = 0.f; o[7] = 0.f;
}

__global__ void k_init3(const float* __restrict__ h3, const float* __restrict__ b,
                        float* __restrict__ agg, int n) {
    int row = blockIdx.x * blockDim.x + threadIdx.x;
    if (row >= n) return;
    float di = g_dinv[row];
    float w = di * di;
    const float* hr = h3 + (size_t)row * 8;
    float* ar = agg + (size_t)row * 8;
#pragma unroll
    for (int j = 0; j < 6; j++) ar[j] = fmaf(hr[j], w, b[j]);
    ar[6] = 0.f; ar[7] = 0.f;
}

// 2 threads per edge: q=0 -> cols 0..3 (v4), q=1 -> cols 4..5 (v2)
__global__ void k_scatter3(const float* __restrict__ h3, float* __restrict__ agg, int e) {
    int t = blockIdx.x * blockDim.x + threadIdx.x;
    if (t >= e * 2) return;
    int edge = t >> 1, q = t & 1;
    int s = g_src[edge], d = g_dst[edge];
    float w = g_norm[edge];
    if (q == 0) {
        float4 v = *(const float4*)(h3 + (size_t)s * 8);
        red_add_v4(agg + (size_t)d * 8, v.x * w, v.y * w, v.z * w, v.w * w);
    } else {
        float2 v = *(const float2*)(h3 + (size_t)s * 8 + 4);
        red_add_v2(agg + (size_t)d * 8 + 4, v.x * w, v.y * w);
    }
}

// ---------------- log_softmax over 6 classes ----------------
__global__ void k_log_softmax(const float* __restrict__ agg, float* __restrict__ out, int n) {
    int row = blockIdx.x * blockDim.x + threadIdx.x;
    if (row >= n) return;
    const float* a = agg + (size_t)row * 8;
    float v[6];
    float m = -1e30f;
#pragma unroll
    for (int j = 0; j < 6; j++) { v[j] = a[j]; m = fmaxf(m, v[j]); }
    float s = 0.f;
#pragma unroll
    for (int j = 0; j < 6; j++) s += expf(v[j] - m);
    float ls = m + logf(s);
    float* o = out + (size_t)row * 6;
#pragma unroll
    for (int j = 0; j < 6; j++) o[j] = v[j] - ls;
}

// ---------------------------------------------------------------------------
static inline int cdiv(long long a, int b) { return (int)((a + b - 1) / b); }

extern "C" void kernel_launch(void* const* d_in, const int* in_sizes, int n_in,
                              void* d_out, int out_size) {
    const float* x  = (const float*)d_in[0];
    const void*  ei = d_in[1];
    const float* W1 = (const float*)d_in[2];
    const float* b1 = (const float*)d_in[3];
    const float* W2 = (const float*)d_in[4];
    const float* b2 = (const float*)d_in[5];
    const float* W3 = (const float*)d_in[6];
    const float* b3 = (const float*)d_in[7];
    float* out = (float*)d_out;

    int n = in_sizes[0] / 128;
    int e = in_sizes[1] / 2;

    float *pA, *pB, *pH3, *pAgg3;
    cudaGetSymbolAddress((void**)&pA,    g_bufA);
    cudaGetSymbolAddress((void**)&pB,    g_bufB);
    cudaGetSymbolAddress((void**)&pH3,   g_h3);
    cudaGetSymbolAddress((void**)&pAgg3, g_agg3);

    const int T = 256;

    // ---- graph preprocessing (shared across all 3 layers) ----
    k_detect_dtype<<<1, 32>>>(ei, e, n);
    k_init_deg<<<cdiv(n, T), T>>>(n);
    k_convert_count<<<cdiv(e, T), T>>>(ei, e);
    k_rsqrt<<<cdiv(n, T), T>>>(n);
    k_edge_norm<<<cdiv(e, T), T>>>(e);

    // ---- layer 1: x(128) -> 64 ----
    k_gemm64<128, false><<<cdiv((long long)n * 32, T), T>>>(x, W1, pA, n);  // 8 warps*4 rows
    k_init64<<<cdiv((long long)n * 16, T), T>>>(pA, b1, pB, n);
    k_scatter64<<<cdiv((long long)e * 16, T), T>>>(pA, pB, e);

    // ---- layer 2: relu(B)(64) -> 64 ----
    k_gemm64<64, true><<<cdiv((long long)n * 32, T), T>>>(pB, W2, pA, n);
    k_init64<<<cdiv((long long)n * 16, T), T>>>(pA, b2, pB, n);
    k_scatter64<<<cdiv((long long)e * 16, T), T>>>(pA, pB, e);

    // ---- layer 3: relu(B)(64) -> 6 (padded to 8) ----
    k_gemm3<<<cdiv(n, 128), 128>>>(pB, W3, pH3, n);
    k_init3<<<cdiv(n, T), T>>>(pH3, b3, pAgg3, n);
    k_scatter3<<<cdiv((long long)e * 2, T), T>>>(pH3, pAgg3, e);

    // ---- log_softmax ----
    k_log_softmax<<<cdiv(n, T), T>>>(pAgg3, out, n);
}

// round 2
// speedup vs baseline: 1.5186x; 1.5186x over previous
#include <cuda_runtime.h>
#include <cstdint>
#include <math_constants.h>

// ---------------------------------------------------------------------------
// GCNNet: 3-layer GCN + log_softmax, CSR-gather formulation (no scatter atomics).
// Per layer: h = in @ W ; agg[i] = h[i]*dinv[i]^2 + b + sum_{e: dst=i} h[src_e]*norm_e
// Shapes: N=100000, E=3200000, din=128, dh=64, dout=6.
// ---------------------------------------------------------------------------

#define MAXN 100000
#define MAXE 3200000

__device__ __align__(16) float g_dinv[MAXN];
__device__ int   g_src[MAXE];
__device__ int   g_dst[MAXE];
__device__ int   g_count[MAXN];      // in-degree (excl self-loop)
__device__ int   g_segstart[MAXN];   // CSR segment start per node
__device__ int   g_cursor[MAXN];     // fill cursor per node
__device__ int   g_perm_src[MAXE];   // src node per dst-grouped edge slot
__device__ __align__(16) float g_perm_norm[MAXE];
__device__ unsigned long long g_cursor0;
__device__ __align__(16) float g_bufA[(size_t)MAXN * 64];
__device__ __align__(16) float g_bufB[(size_t)MAXN * 64];
__device__ __align__(16) float g_h3[(size_t)MAXN * 8];
__device__ int   g_is64;

// ---------------- setup ----------------
__global__ void k_detect_dtype(const void* ei, int e, int n) {
    if (blockIdx.x == 0 && threadIdx.x == 0) {
        // int64 buffer: every 8-byte word is in [0, n). int32 buffer: the
        // 8-byte view packs two ids (>= 2^32 unless hi word happens to be 0).
        const long long* p = (const long long*)ei;
        int m = e < 1024 ? e : 1024;
        int ok = 1;
        for (int i = 0; i < m; i++) {
            long long v = p[i];
            if (v < 0 || v >= (long long)n) { ok = 0; break; }
        }
        g_is64 = ok;
    }
}

__global__ void k_zero(int n) {
    int i = blockIdx.x * blockDim.x + threadIdx.x;
    if (i < n) g_count[i] = 0;
    if (i == 0) g_cursor0 = 0ull;
}

// convert edge index to int32 and histogram in-degree per dst
__global__ void k_convert_hist(const void* ei, int e) {
    int i = blockIdx.x * blockDim.x + threadIdx.x;
    if (i >= e) return;
    int s, d;
    if (g_is64) {
        const long long* p = (const long long*)ei;
        s = (int)p[i];
        d = (int)p[e + i];
    } else {
        const int* p = (const int*)ei;
        s = p[i];
        d = p[e + i];
    }
    g_src[i] = s;
    g_dst[i] = d;
    atomicAdd(&g_count[d], 1);
}

// allocate CSR segments (warp-aggregated cursor bump; segment order arbitrary),
// compute dinv = rsqrt(deg) with the +1 self-loop
__global__ void k_segments(int n) {
    int i = blockIdx.x * blockDim.x + threadIdx.x;
    int lane = threadIdx.x & 31;
    int c = (i < n) ? g_count[i] : 0;
    // warp inclusive scan of c
    int incl = c;
#pragma unroll
    for (int off = 1; off < 32; off <<= 1) {
        int v = __shfl_up_sync(0xffffffff, incl, off);
        if (lane >= off) incl += v;
    }
    int total = __shfl_sync(0xffffffff, incl, 31);
    unsigned long long base = 0;
    if (lane == 31) base = atomicAdd(&g_cursor0, (unsigned long long)total);
    base = __shfl_sync(0xffffffff, base, 31);
    if (i < n) {
        int start = (int)base + incl - c;
        g_segstart[i] = start;
        g_cursor[i]   = start;
        g_dinv[i]     = rsqrtf((float)(c + 1));
    }
}

// scatter edges into dst-grouped slots, precompute per-edge norm
__global__ void k_permute(int e) {
    int i = blockIdx.x * blockDim.x + threadIdx.x;
    if (i >= e) return;
    int s = g_src[i], d = g_dst[i];
    int pos = atomicAdd(&g_cursor[d], 1);
    g_perm_src[pos]  = s;
    g_perm_norm[pos] = g_dinv[s] * g_dinv[d];
}

// ---------------- GEMM: [n, K] @ [K, 64] -> [n, 64] ----------------
template <int K>
__global__ void k_gemm64(const float* __restrict__ in, const float* __restrict__ W,
                         float* __restrict__ out, int n) {
    __shared__ float Ws[K * 64];
    for (int i = threadIdx.x; i < K * 64; i += blockDim.x) Ws[i] = W[i];
    __syncthreads();

    int warp = (blockIdx.x * blockDim.x + threadIdx.x) >> 5;
    int lane = threadIdx.x & 31;
    int row0 = warp * 4;
    if (row0 >= n) return;
    int rows = n - row0; if (rows > 4) rows = 4;

    float acc[4][2] = {};
    for (int k = 0; k < K; k += 4) {
        float4 xv[4];
#pragma unroll
        for (int r = 0; r < 4; r++)
            xv[r] = (r < rows) ? *(const float4*)(in + (size_t)(row0 + r) * K + k)
                               : make_float4(0.f, 0.f, 0.f, 0.f);
#pragma unroll
        for (int kk = 0; kk < 4; kk++) {
            float w0 = Ws[(k + kk) * 64 + lane];
            float w1 = Ws[(k + kk) * 64 + lane + 32];
#pragma unroll
            for (int r = 0; r < 4; r++) {
                float x = (kk == 0) ? xv[r].x : (kk == 1) ? xv[r].y
                        : (kk == 2) ? xv[r].z : xv[r].w;
                acc[r][0] = fmaf(x, w0, acc[r][0]);
                acc[r][1] = fmaf(x, w1, acc[r][1]);
            }
        }
    }
#pragma unroll
    for (int r = 0; r < 4; r++) {
        if (r < rows) {
            out[(size_t)(row0 + r) * 64 + lane]      = acc[r][0];
            out[(size_t)(row0 + r) * 64 + lane + 32] = acc[r][1];
        }
    }
}

// ---------------- CSR gather, 64-wide: warp per node, float2 per lane -------
// agg[i] = relu?( h[i]*dinv^2 + b + sum_e h[perm_src[e]]*perm_norm[e] )
template <bool RELU>
__global__ void k_gather64(const float* __restrict__ h, const float* __restrict__ b,
                           float* __restrict__ agg, int n) {
    int warp = (blockIdx.x * blockDim.x + threadIdx.x) >> 5;
    int lane = threadIdx.x & 31;
    if (warp >= n) return;
    int node = warp;
    int c = lane * 2;

    float di = g_dinv[node];
    float w0 = di * di;
    float2 acc = *(const float2*)(h + (size_t)node * 64 + c);
    float2 bb  = *(const float2*)(b + c);
    acc.x = fmaf(acc.x, w0, bb.x);
    acc.y = fmaf(acc.y, w0, bb.y);

    int p   = g_segstart[node];
    int end = p + g_count[node];

    for (; p + 4 <= end; p += 4) {
        int   s0 = g_perm_src[p],     s1 = g_perm_src[p + 1];
        int   s2 = g_perm_src[p + 2], s3 = g_perm_src[p + 3];
        float n0 = g_perm_norm[p],     n1 = g_perm_norm[p + 1];
        float n2 = g_perm_norm[p + 2], n3 = g_perm_norm[p + 3];
        float2 v0 = *(const float2*)(h + (size_t)s0 * 64 + c);
        float2 v1 = *(const float2*)(h + (size_t)s1 * 64 + c);
        float2 v2 = *(const float2*)(h + (size_t)s2 * 64 + c);
        float2 v3 = *(const float2*)(h + (size_t)s3 * 64 + c);
        acc.x = fmaf(v0.x, n0, acc.x); acc.y = fmaf(v0.y, n0, acc.y);
        acc.x = fmaf(v1.x, n1, acc.x); acc.y = fmaf(v1.y, n1, acc.y);
        acc.x = fmaf(v2.x, n2, acc.x); acc.y = fmaf(v2.y, n2, acc.y);
        acc.x = fmaf(v3.x, n3, acc.x); acc.y = fmaf(v3.y, n3, acc.y);
    }
    for (; p < end; p++) {
        int s = g_perm_src[p];
        float nw = g_perm_norm[p];
        float2 v = *(const float2*)(h + (size_t)s * 64 + c);
        acc.x = fmaf(v.x, nw, acc.x);
        acc.y = fmaf(v.y, nw, acc.y);
    }
    if (RELU) { acc.x = fmaxf(acc.x, 0.f); acc.y = fmaxf(acc.y, 0.f); }
    *(float2*)(agg + (size_t)node * 64 + c) = acc;
}

// ---------------- layer 3: [n,64] @ [64,6] -> [n,8] (padded) ----------------
__global__ void k_gemm3(const float* __restrict__ in, const float* __restrict__ W,
                        float* __restrict__ out, int n) {
    __shared__ float Ws[64 * 6];
    for (int i = threadIdx.x; i < 64 * 6; i += blockDim.x) Ws[i] = W[i];
    __syncthreads();
    int row = blockIdx.x * blockDim.x + threadIdx.x;
    if (row >= n) return;
    float acc[6] = {};
    const float* xr = in + (size_t)row * 64;
    for (int k = 0; k < 64; k++) {
        float x = xr[k];
#pragma unroll
        for (int j = 0; j < 6; j++) acc[j] = fmaf(x, Ws[k * 6 + j], acc[j]);
    }
    float* o = out + (size_t)row * 8;
#pragma unroll
    for (int j = 0; j < 6; j++) o[j] = acc[j];
    o[6] = 0.f; o[7] = 0.f;
}

// ---------------- layer-3 gather (8 lanes/node) + fused log_softmax ---------
__global__ void k_gather3_softmax(const float* __restrict__ h3, const float* __restrict__ b,
                                  float* __restrict__ out, int n) {
    int t = blockIdx.x * blockDim.x + threadIdx.x;
    int node = t >> 3;
    int col  = t & 7;
    bool active = (node < n);
    int nd = active ? node : 0;

    float di = g_dinv[nd];
    float w0 = di * di;
    float acc = h3[(size_t)nd * 8 + col];
    float bb  = (col < 6) ? b[col] : 0.f;
    acc = fmaf(acc, w0, bb);

    int p   = active ? g_segstart[nd] : 0;
    int end = active ? p + g_count[nd] : 0;
    for (; p < end; p++) {
        int s = g_perm_src[p];
        float nw = g_perm_norm[p];
        acc = fmaf(h3[(size_t)s * 8 + col], nw, acc);
    }

    // log_softmax across 6 cols held by lanes 0..5 of each 8-lane group
    float m = (col < 6) ? acc : -CUDART_INF_F;
#pragma unroll
    for (int off = 4; off >= 1; off >>= 1)
        m = fmaxf(m, __shfl_xor_sync(0xffffffff, m, off, 8));
    float ex = (col < 6) ? expf(acc - m) : 0.f;
#pragma unroll
    for (int off = 4; off >= 1; off >>= 1)
        ex += __shfl_xor_sync(0xffffffff, ex, off, 8);
    float ls = m + logf(ex);
    if (active && col < 6)
        out[(size_t)node * 6 + col] = acc - ls;
}

// ---------------------------------------------------------------------------
static inline int cdiv(long long a, int b) { return (int)((a + b - 1) / b); }

extern "C" void kernel_launch(void* const* d_in, const int* in_sizes, int n_in,
                              void* d_out, int out_size) {
    const float* x  = (const float*)d_in[0];
    const void*  ei = d_in[1];
    const float* W1 = (const float*)d_in[2];
    const float* b1 = (const float*)d_in[3];
    const float* W2 = (const float*)d_in[4];
    const float* b2 = (const float*)d_in[5];
    const float* W3 = (const float*)d_in[6];
    const float* b3 = (const float*)d_in[7];
    float* out = (float*)d_out;

    int n = in_sizes[0] / 128;
    int e = in_sizes[1] / 2;

    float *pA, *pB, *pH3;
    cudaGetSymbolAddress((void**)&pA,  g_bufA);
    cudaGetSymbolAddress((void**)&pB,  g_bufB);
    cudaGetSymbolAddress((void**)&pH3, g_h3);

    const int T = 256;

    // ---- CSR build (shared across all 3 layers) ----
    k_detect_dtype<<<1, 32>>>(ei, e, n);
    k_zero<<<cdiv(n, T), T>>>(n);
    k_convert_hist<<<cdiv(e, T), T>>>(ei, e);
    k_segments<<<cdiv(n, T), T>>>(n);
    k_permute<<<cdiv(e, T), T>>>(e);

    // ---- layer 1: x(128) -> 64 ----
    k_gemm64<128><<<cdiv((long long)n * 32, T), T>>>(x, W1, pA, n);
    k_gather64<true><<<cdiv((long long)n * 32, T), T>>>(pA, b1, pB, n);

    // ---- layer 2: 64 -> 64 ----
    k_gemm64<64><<<cdiv((long long)n * 32, T), T>>>(pB, W2, pA, n);
    k_gather64<true><<<cdiv((long long)n * 32, T), T>>>(pA, b2, pB, n);

    // ---- layer 3: 64 -> 6 (padded 8) + softmax ----
    k_gemm3<<<cdiv(n, 128), 128>>>(pB, W3, pH3, n);
    k_gather3_softmax<<<cdiv((long long)n * 8, T), T>>>(pH3, b3, out, n);
}

// round 3
// speedup vs baseline: 1.5793x; 1.0400x over previous
#include <cuda_runtime.h>
#include <cuda_fp16.h>
#include <cstdint>
#include <math_constants.h>

// ---------------------------------------------------------------------------
// GCNNet: 3-layer GCN + log_softmax, CSR-gather formulation, fp16 feature rows.
// Per layer: h = in @ W (fp16 out); agg[i] = h[i]*dinv^2 + b + sum h[src]*norm
// Shapes: N=100000, E=3200000, din=128, dh=64, dout=6.
// ---------------------------------------------------------------------------

#define MAXN 100000
#define MAXE 3200000

__device__ __align__(16) float g_dinv[MAXN];
__device__ int   g_src[MAXE];
__device__ int   g_dst[MAXE];
__device__ int   g_count[MAXN];      // in-degree (excl self-loop)
__device__ int   g_segstart[MAXN];
__device__ int   g_cursor[MAXN];
__device__ __align__(16) float2 g_perm[MAXE];   // .x = src id (bits), .y = norm
__device__ unsigned long long g_cursor0;
__device__ __align__(16) __half g_hA[(size_t)MAXN * 64];   // fp16 gemm output (gather src)
__device__ __align__(16) float  g_aggB[(size_t)MAXN * 64]; // fp32 gather output (gemm in)
__device__ __align__(16) __half g_h3[(size_t)MAXN * 8];
__device__ int   g_is64;

// ---------------- setup ----------------
__global__ void k_detect_dtype(const void* ei, int e, int n) {
    if (blockIdx.x == 0 && threadIdx.x == 0) {
        // int64 buffer: every 8-byte word is in [0, n). int32 buffer: the
        // 8-byte view packs two ids (>= 2^32 unless hi word happens to be 0).
        const long long* p = (const long long*)ei;
        int m = e < 1024 ? e : 1024;
        int ok = 1;
        for (int i = 0; i < m; i++) {
            long long v = p[i];
            if (v < 0 || v >= (long long)n) { ok = 0; break; }
        }
        g_is64 = ok;
    }
}

__global__ void k_zero(int n) {
    int i = blockIdx.x * blockDim.x + threadIdx.x;
    if (i < n) g_count[i] = 0;
    if (i == 0) g_cursor0 = 0ull;
}

__global__ void k_convert_hist(const void* ei, int e) {
    int i = blockIdx.x * blockDim.x + threadIdx.x;
    if (i >= e) return;
    int s, d;
    if (g_is64) {
        const long long* p = (const long long*)ei;
        s = (int)p[i];
        d = (int)p[e + i];
    } else {
        const int* p = (const int*)ei;
        s = p[i];
        d = p[e + i];
    }
    g_src[i] = s;
    g_dst[i] = d;
    atomicAdd(&g_count[d], 1);
}

// allocate CSR segments; dinv = rsqrt(deg+1) (self-loop)
__global__ void k_segments(int n) {
    int i = blockIdx.x * blockDim.x + threadIdx.x;
    int lane = threadIdx.x & 31;
    int c = (i < n) ? g_count[i] : 0;
    int incl = c;
#pragma unroll
    for (int off = 1; off < 32; off <<= 1) {
        int v = __shfl_up_sync(0xffffffff, incl, off);
        if (lane >= off) incl += v;
    }
    int total = __shfl_sync(0xffffffff, incl, 31);
    unsigned long long base = 0;
    if (lane == 31) base = atomicAdd(&g_cursor0, (unsigned long long)total);
    base = __shfl_sync(0xffffffff, base, 31);
    if (i < n) {
        int start = (int)base + incl - c;
        g_segstart[i] = start;
        g_cursor[i]   = start;
        g_dinv[i]     = rsqrtf((float)(c + 1));
    }
}

__global__ void k_permute(int e) {
    int i = blockIdx.x * blockDim.x + threadIdx.x;
    if (i >= e) return;
    int s = g_src[i], d = g_dst[i];
    int pos = atomicAdd(&g_cursor[d], 1);
    g_perm[pos] = make_float2(__int_as_float(s), g_dinv[s] * g_dinv[d]);
}

// ---------------- GEMM: [n, K] fp32 @ [K, 64] -> [n, 64] fp16 ----------------
template <int K>
__global__ void k_gemm64(const float* __restrict__ in, const float* __restrict__ W,
                         __half* __restrict__ out, int n) {
    __shared__ float Ws[K * 64];
    for (int i = threadIdx.x; i < K * 64; i += blockDim.x) Ws[i] = W[i];
    __syncthreads();

    int warp = (blockIdx.x * blockDim.x + threadIdx.x) >> 5;
    int lane = threadIdx.x & 31;
    int row0 = warp * 4;
    if (row0 >= n) return;
    int rows = n - row0; if (rows > 4) rows = 4;

    float acc[4][2] = {};
    for (int k = 0; k < K; k += 4) {
        float4 xv[4];
#pragma unroll
        for (int r = 0; r < 4; r++)
            xv[r] = (r < rows) ? *(const float4*)(in + (size_t)(row0 + r) * K + k)
                               : make_float4(0.f, 0.f, 0.f, 0.f);
#pragma unroll
        for (int kk = 0; kk < 4; kk++) {
            float w0 = Ws[(k + kk) * 64 + lane];
            float w1 = Ws[(k + kk) * 64 + lane + 32];
#pragma unroll
            for (int r = 0; r < 4; r++) {
                float x = (kk == 0) ? xv[r].x : (kk == 1) ? xv[r].y
                        : (kk == 2) ? xv[r].z : xv[r].w;
                acc[r][0] = fmaf(x, w0, acc[r][0]);
                acc[r][1] = fmaf(x, w1, acc[r][1]);
            }
        }
    }
#pragma unroll
    for (int r = 0; r < 4; r++) {
        if (r < rows) {
            out[(size_t)(row0 + r) * 64 + lane]      = __float2half(acc[r][0]);
            out[(size_t)(row0 + r) * 64 + lane + 32] = __float2half(acc[r][1]);
        }
    }
}

// ---------------- CSR gather, 64-wide: warp/node, half2/lane, fp32 accum ----
template <bool RELU>
__global__ void k_gather64(const __half* __restrict__ h, const float* __restrict__ b,
                           float* __restrict__ agg, int n) {
    int warp = (blockIdx.x * blockDim.x + threadIdx.x) >> 5;
    int lane = threadIdx.x & 31;
    if (warp >= n) return;
    int node = warp;
    int c = lane * 2;

    float di = g_dinv[node];
    float w0 = di * di;
    float2 self = __half22float2(*(const half2*)(h + (size_t)node * 64 + c));
    float2 bb   = *(const float2*)(b + c);
    float2 acc;
    acc.x = fmaf(self.x, w0, bb.x);
    acc.y = fmaf(self.y, w0, bb.y);

    int p   = g_segstart[node];
    int end = p + g_count[node];

    for (; p + 4 <= end; p += 4) {
        float2 e0 = g_perm[p],     e1 = g_perm[p + 1];
        float2 e2 = g_perm[p + 2], e3 = g_perm[p + 3];
        float2 v0 = __half22float2(*(const half2*)(h + (size_t)__float_as_int(e0.x) * 64 + c));
        float2 v1 = __half22float2(*(const half2*)(h + (size_t)__float_as_int(e1.x) * 64 + c));
        float2 v2 = __half22float2(*(const half2*)(h + (size_t)__float_as_int(e2.x) * 64 + c));
        float2 v3 = __half22float2(*(const half2*)(h + (size_t)__float_as_int(e3.x) * 64 + c));
        acc.x = fmaf(v0.x, e0.y, acc.x); acc.y = fmaf(v0.y, e0.y, acc.y);
        acc.x = fmaf(v1.x, e1.y, acc.x); acc.y = fmaf(v1.y, e1.y, acc.y);
        acc.x = fmaf(v2.x, e2.y, acc.x); acc.y = fmaf(v2.y, e2.y, acc.y);
        acc.x = fmaf(v3.x, e3.y, acc.x); acc.y = fmaf(v3.y, e3.y, acc.y);
    }
    for (; p < end; p++) {
        float2 ee = g_perm[p];
        float2 v = __half22float2(*(const half2*)(h + (size_t)__float_as_int(ee.x) * 64 + c));
        acc.x = fmaf(v.x, ee.y, acc.x);
        acc.y = fmaf(v.y, ee.y, acc.y);
    }
    if (RELU) { acc.x = fmaxf(acc.x, 0.f); acc.y = fmaxf(acc.y, 0.f); }
    *(float2*)(agg + (size_t)node * 64 + c) = acc;
}

// ---------------- layer 3: [n,64] @ [64,6] -> [n,8] fp16 (padded) -----------
__global__ void k_gemm3(const float* __restrict__ in, const float* __restrict__ W,
                        __half* __restrict__ out, int n) {
    __shared__ float Ws[64 * 6];
    for (int i = threadIdx.x; i < 64 * 6; i += blockDim.x) Ws[i] = W[i];
    __syncthreads();
    int row = blockIdx.x * blockDim.x + threadIdx.x;
    if (row >= n) return;
    float acc[6] = {};
    const float* xr = in + (size_t)row * 64;
    for (int k = 0; k < 64; k++) {
        float x = xr[k];
#pragma unroll
        for (int j = 0; j < 6; j++) acc[j] = fmaf(x, Ws[k * 6 + j], acc[j]);
    }
    __half* o = out + (size_t)row * 8;
#pragma unroll
    for (int j = 0; j < 6; j++) o[j] = __float2half(acc[j]);
    o[6] = __float2half(0.f); o[7] = __float2half(0.f);
}

// ---------------- layer-3 gather (8 lanes/node) + fused log_softmax ---------
__global__ void k_gather3_softmax(const __half* __restrict__ h3, const float* __restrict__ b,
                                  float* __restrict__ out, int n) {
    int t = blockIdx.x * blockDim.x + threadIdx.x;
    int node = t >> 3;
    int col  = t & 7;
    bool active = (node < n);
    int nd = active ? node : 0;

    float di = g_dinv[nd];
    float w0 = di * di;
    float acc = __half2float(h3[(size_t)nd * 8 + col]);
    float bb  = (col < 6) ? b[col] : 0.f;
    acc = fmaf(acc, w0, bb);

    int p   = active ? g_segstart[nd] : 0;
    int end = active ? p + g_count[nd] : 0;
    for (; p < end; p++) {
        float2 ee = g_perm[p];
        acc = fmaf(__half2float(h3[(size_t)__float_as_int(ee.x) * 8 + col]), ee.y, acc);
    }

    float m = (col < 6) ? acc : -CUDART_INF_F;
#pragma unroll
    for (int off = 4; off >= 1; off >>= 1)
        m = fmaxf(m, __shfl_xor_sync(0xffffffff, m, off, 8));
    float ex = (col < 6) ? expf(acc - m) : 0.f;
#pragma unroll
    for (int off = 4; off >= 1; off >>= 1)
        ex += __shfl_xor_sync(0xffffffff, ex, off, 8);
    float ls = m + logf(ex);
    if (active && col < 6)
        out[(size_t)node * 6 + col] = acc - ls;
}

// ---------------------------------------------------------------------------
static inline int cdiv(long long a, int b) { return (int)((a + b - 1) / b); }

extern "C" void kernel_launch(void* const* d_in, const int* in_sizes, int n_in,
                              void* d_out, int out_size) {
    const float* x  = (const float*)d_in[0];
    const void*  ei = d_in[1];
    const float* W1 = (const float*)d_in[2];
    const float* b1 = (const float*)d_in[3];
    const float* W2 = (const float*)d_in[4];
    const float* b2 = (const float*)d_in[5];
    const float* W3 = (const float*)d_in[6];
    const float* b3 = (const float*)d_in[7];
    float* out = (float*)d_out;

    int n = in_sizes[0] / 128;
    int e = in_sizes[1] / 2;

    __half *pHA, *pH3;
    float  *pAgg;
    cudaGetSymbolAddress((void**)&pHA,  g_hA);
    cudaGetSymbolAddress((void**)&pAgg, g_aggB);
    cudaGetSymbolAddress((void**)&pH3,  g_h3);

    const int T = 256;

    // ---- CSR build (shared across all 3 layers) ----
    k_detect_dtype<<<1, 32>>>(ei, e, n);
    k_zero<<<cdiv(n, T), T>>>(n);
    k_convert_hist<<<cdiv(e, T), T>>>(ei, e);
    k_segments<<<cdiv(n, T), T>>>(n);
    k_permute<<<cdiv(e, T), T>>>(e);

    // ---- layer 1: x(128) -> 64 ----
    k_gemm64<128><<<cdiv((long long)n * 32, T), T>>>(x, W1, pHA, n);
    k_gather64<true><<<cdiv((long long)n * 32, T), T>>>(pHA, b1, pAgg, n);

    // ---- layer 2: 64 -> 64 ----
    k_gemm64<64><<<cdiv((long long)n * 32, T), T>>>(pAgg, W2, pHA, n);
    k_gather64<true><<<cdiv((long long)n * 32, T), T>>>(pHA, b2, pAgg, n);

    // ---- layer 3: 64 -> 6 (padded 8) + softmax ----
    k_gemm3<<<cdiv(n, 128), 128>>>(pAgg, W3, pH3, n);
    k_gather3_softmax<<<cdiv((long long)n * 8, T), T>>>(pH3, b3, out, n);
}

// round 4
// speedup vs baseline: 1.9620x; 1.2423x over previous
#include <cuda_runtime.h>
#include <cuda_fp16.h>
#include <cstdint>
#include <math_constants.h>

// ---------------------------------------------------------------------------
// GCNNet: 3-layer GCN + log_softmax. CSR gather, fp16 rows, LDG.128 gathers,
// packed fp32x2 FMA (sm_103a FFMA2).
// ---------------------------------------------------------------------------

#define MAXN 100000
#define MAXE 3200000

__device__ float g_dinv[MAXN];
__device__ int   g_src[MAXE];
__device__ int   g_dst[MAXE];
__device__ int   g_count[MAXN];
__device__ int   g_segstart[MAXN];
__device__ int   g_cursor[MAXN];
__device__ __align__(16) float2 g_perm[MAXE];   // .x = src id bits, .y = norm
__device__ unsigned long long g_cursor0;
__device__ __align__(16) __half g_hA[(size_t)MAXN * 64];    // gemm out (gather src)
__device__ __align__(16) float  g_aggB[(size_t)MAXN * 64];  // gather out fp32
__device__ __align__(16) __half g_agg16[(size_t)MAXN * 64]; // gather out fp16 (L2)
__device__ __align__(16) __half g_h3[(size_t)MAXN * 8];
__device__ int g_is64;

// packed fp32x2 FMA (Blackwell FFMA2)
__device__ __forceinline__ float2 fma2(float2 a, float2 b, float2 c) {
    float2 d;
    asm("{\n\t"
        ".reg .b64 ra, rb, rc, rd;\n\t"
        "mov.b64 ra, {%2, %3};\n\t"
        "mov.b64 rb, {%4, %5};\n\t"
        "mov.b64 rc, {%6, %7};\n\t"
        "fma.rn.f32x2 rd, ra, rb, rc;\n\t"
        "mov.b64 {%0, %1}, rd;\n\t"
        "}"
        : "=f"(d.x), "=f"(d.y)
        : "f"(a.x), "f"(a.y), "f"(b.x), "f"(b.y), "f"(c.x), "f"(c.y));
    return d;
}

// ---------------- setup ----------------
// zero counters + parallel dtype probe (block 0)
__global__ void k_detect_zero(const void* ei, int e, int n) {
    int i = blockIdx.x * blockDim.x + threadIdx.x;
    if (i < n) g_count[i] = 0;
    if (i == 0) g_cursor0 = 0ull;
    if (blockIdx.x == 0) {
        // int64 buffer: every 8-byte word is in [0, n). int32 buffer: 8-byte
        // view packs two ids (>= 2^32 unless the hi id happens to be 0).
        const long long* p = (const long long*)ei;
        int m = e < 1024 ? e : 1024;
        int bad = 0;
        for (int q = threadIdx.x; q < m; q += blockDim.x) {
            long long v = p[q];
            if (v < 0 || v >= (long long)n) bad = 1;
        }
        bad = __syncthreads_or(bad);
        if (threadIdx.x == 0) g_is64 = !bad;
    }
}

__global__ void k_convert_hist(const void* ei, int e) {
    int i = blockIdx.x * blockDim.x + threadIdx.x;
    if (i >= e) return;
    int s, d;
    if (g_is64) {
        const long long* p = (const long long*)ei;
        s = (int)p[i];
        d = (int)p[e + i];
    } else {
        const int* p = (const int*)ei;
        s = p[i];
        d = p[e + i];
    }
    g_src[i] = s;
    g_dst[i] = d;
    atomicAdd(&g_count[d], 1);
}

__global__ void k_segments(int n) {
    int i = blockIdx.x * blockDim.x + threadIdx.x;
    int lane = threadIdx.x & 31;
    int c = (i < n) ? g_count[i] : 0;
    int incl = c;
#pragma unroll
    for (int off = 1; off < 32; off <<= 1) {
        int v = __shfl_up_sync(0xffffffff, incl, off);
        if (lane >= off) incl += v;
    }
    int total = __shfl_sync(0xffffffff, incl, 31);
    unsigned long long base = 0;
    if (lane == 31) base = atomicAdd(&g_cursor0, (unsigned long long)total);
    base = __shfl_sync(0xffffffff, base, 31);
    if (i < n) {
        int start = (int)base + incl - c;
        g_segstart[i] = start;
        g_cursor[i]   = start;
        g_dinv[i]     = rsqrtf((float)(c + 1));
    }
}

__global__ void k_permute(int e) {
    int i = blockIdx.x * blockDim.x + threadIdx.x;
    if (i >= e) return;
    int s = g_src[i], d = g_dst[i];
    int pos = atomicAdd(&g_cursor[d], 1);
    g_perm[pos] = make_float2(__int_as_float(s), g_dinv[s] * g_dinv[d]);
}

// ---------------- GEMM: [n,K] fp32 @ [K,64] -> [n,64] fp16, f32x2 packed ----
// K split into even/odd pairs: acc holds (sum_even, sum_odd), reduced at end.
template <int K>
__global__ void k_gemm64(const float* __restrict__ in, const float* __restrict__ W,
                         __half* __restrict__ out, int n) {
    __shared__ float2 Wp[(K / 2) * 64];   // Wp[j][c] = (W[2j][c], W[2j+1][c])
    for (int i = threadIdx.x; i < (K / 2) * 64; i += blockDim.x) {
        int j = i >> 6, cc = i & 63;
        Wp[i] = make_float2(W[(2 * j) * 64 + cc], W[(2 * j + 1) * 64 + cc]);
    }
    __syncthreads();

    int warp = (blockIdx.x * blockDim.x + threadIdx.x) >> 5;
    int lane = threadIdx.x & 31;
    int row0 = warp * 4;
    if (row0 >= n) return;
    int rows = n - row0; if (rows > 4) rows = 4;

    float2 acc[4][2] = {};
    for (int k = 0; k < K; k += 4) {
        int j = k >> 1;
        float4 xv[4];
#pragma unroll
        for (int r = 0; r < 4; r++)
            xv[r] = (r < rows) ? *(const float4*)(in + (size_t)(row0 + r) * K + k)
                               : make_float4(0.f, 0.f, 0.f, 0.f);
        float2 w00 = Wp[j * 64 + lane];
        float2 w01 = Wp[j * 64 + lane + 32];
        float2 w10 = Wp[(j + 1) * 64 + lane];
        float2 w11 = Wp[(j + 1) * 64 + lane + 32];
#pragma unroll
        for (int r = 0; r < 4; r++) {
            float2 a0 = make_float2(xv[r].x, xv[r].y);
            float2 a1 = make_float2(xv[r].z, xv[r].w);
            acc[r][0] = fma2(a0, w00, acc[r][0]);
            acc[r][1] = fma2(a0, w01, acc[r][1]);
            acc[r][0] = fma2(a1, w10, acc[r][0]);
            acc[r][1] = fma2(a1, w11, acc[r][1]);
        }
    }
#pragma unroll
    for (int r = 0; r < 4; r++) {
        if (r < rows) {
            out[(size_t)(row0 + r) * 64 + lane]      = __float2half(acc[r][0].x + acc[r][0].y);
            out[(size_t)(row0 + r) * 64 + lane + 32] = __float2half(acc[r][1].x + acc[r][1].y);
        }
    }
}

// ---------------- CSR gather: 8 lanes/node, LDG.128 rows, shuffled perm -----
template <bool RELU, bool OUT16>
__global__ void k_gather64(const __half* __restrict__ h, const float* __restrict__ b,
                           float* __restrict__ agg, __half* __restrict__ agg16, int n) {
    int tid = blockIdx.x * blockDim.x + threadIdx.x;
    int node = tid >> 3;
    int g = threadIdx.x & 7;
    bool active = (node < n);
    int nd = active ? node : (n - 1);
    int c = g * 8;   // 8 fp16 columns per lane

    float di = g_dinv[nd];
    float2 ww = make_float2(di * di, di * di);
    uint4 sr = *(const uint4*)(h + (size_t)nd * 64 + c);
    float4 b0 = *(const float4*)(b + c);
    float4 b1 = *(const float4*)(b + c + 4);
    float2 acc0 = fma2(__half22float2(*(half2*)&sr.x), ww, make_float2(b0.x, b0.y));
    float2 acc1 = fma2(__half22float2(*(half2*)&sr.y), ww, make_float2(b0.z, b0.w));
    float2 acc2 = fma2(__half22float2(*(half2*)&sr.z), ww, make_float2(b1.x, b1.y));
    float2 acc3 = fma2(__half22float2(*(half2*)&sr.w), ww, make_float2(b1.z, b1.w));

    int p   = active ? g_segstart[nd] : 0;
    int end = active ? (p + g_count[nd]) : 0;

    while (__any_sync(0xffffffffu, p < end)) {
        float2 ee = (p + g < end) ? g_perm[p + g] : make_float2(0.f, 0.f);
        int eis = __float_as_int(ee.x);
#pragma unroll
        for (int j = 0; j < 8; j++) {
            int   s  = __shfl_sync(0xffffffffu, eis, j, 8);
            float nw = __shfl_sync(0xffffffffu, ee.y, j, 8);
            if (p + j < end) {
                uint4 r = *(const uint4*)(h + (size_t)s * 64 + c);
                float2 nn = make_float2(nw, nw);
                acc0 = fma2(__half22float2(*(half2*)&r.x), nn, acc0);
                acc1 = fma2(__half22float2(*(half2*)&r.y), nn, acc1);
                acc2 = fma2(__half22float2(*(half2*)&r.z), nn, acc2);
                acc3 = fma2(__half22float2(*(half2*)&r.w), nn, acc3);
            }
        }
        p += 8;
    }
    if (!active) return;
    if (RELU) {
        acc0.x = fmaxf(acc0.x, 0.f); acc0.y = fmaxf(acc0.y, 0.f);
        acc1.x = fmaxf(acc1.x, 0.f); acc1.y = fmaxf(acc1.y, 0.f);
        acc2.x = fmaxf(acc2.x, 0.f); acc2.y = fmaxf(acc2.y, 0.f);
        acc3.x = fmaxf(acc3.x, 0.f); acc3.y = fmaxf(acc3.y, 0.f);
    }
    if (OUT16) {
        uint4 o;
        *(half2*)&o.x = __float22half2_rn(acc0);
        *(half2*)&o.y = __float22half2_rn(acc1);
        *(half2*)&o.z = __float22half2_rn(acc2);
        *(half2*)&o.w = __float22half2_rn(acc3);
        *(uint4*)(agg16 + (size_t)node * 64 + c) = o;
    } else {
        *(float4*)(agg + (size_t)node * 64 + c)     = make_float4(acc0.x, acc0.y, acc1.x, acc1.y);
        *(float4*)(agg + (size_t)node * 64 + c + 4) = make_float4(acc2.x, acc2.y, acc3.x, acc3.y);
    }
}

// ---------------- layer 3: [n,64] fp16 @ [64,6] -> [n,8] fp16 ----------------
__global__ void k_gemm3(const __half* __restrict__ in, const float* __restrict__ W,
                        __half* __restrict__ out, int n) {
    __shared__ float Ws[64 * 6];
    for (int i = threadIdx.x; i < 64 * 6; i += blockDim.x) Ws[i] = W[i];
    __syncthreads();
    int row = blockIdx.x * blockDim.x + threadIdx.x;
    if (row >= n) return;
    const uint4* xr = (const uint4*)(in + (size_t)row * 64);
    float acc[6] = {};
#pragma unroll
    for (int q = 0; q < 8; q++) {
        uint4 u = xr[q];
        float2 f0 = __half22float2(*(half2*)&u.x);
        float2 f1 = __half22float2(*(half2*)&u.y);
        float2 f2 = __half22float2(*(half2*)&u.z);
        float2 f3 = __half22float2(*(half2*)&u.w);
        float xs[8] = {f0.x, f0.y, f1.x, f1.y, f2.x, f2.y, f3.x, f3.y};
#pragma unroll
        for (int t = 0; t < 8; t++) {
            int k = q * 8 + t;
#pragma unroll
            for (int jj = 0; jj < 6; jj++)
                acc[jj] = fmaf(xs[t], Ws[k * 6 + jj], acc[jj]);
        }
    }
    __half* o = out + (size_t)row * 8;
#pragma unroll
    for (int jj = 0; jj < 6; jj++) o[jj] = __float2half(acc[jj]);
    o[6] = __float2half(0.f); o[7] = __float2half(0.f);
}

// ---------------- layer-3 gather (8 lanes/node) + fused log_softmax ---------
__global__ void k_gather3_softmax(const __half* __restrict__ h3, const float* __restrict__ b,
                                  float* __restrict__ out, int n) {
    int t = blockIdx.x * blockDim.x + threadIdx.x;
    int node = t >> 3;
    int col  = t & 7;
    bool active = (node < n);
    int nd = active ? node : 0;

    float di = g_dinv[nd];
    float w0 = di * di;
    float acc = __half2float(h3[(size_t)nd * 8 + col]);
    float bb  = (col < 6) ? b[col] : 0.f;
    acc = fmaf(acc, w0, bb);

    int p   = active ? g_segstart[nd] : 0;
    int end = active ? p + g_count[nd] : 0;
    for (; p < end; p++) {
        float2 ee = g_perm[p];
        acc = fmaf(__half2float(h3[(size_t)__float_as_int(ee.x) * 8 + col]), ee.y, acc);
    }

    float m = (col < 6) ? acc : -CUDART_INF_F;
#pragma unroll
    for (int off = 4; off >= 1; off >>= 1)
        m = fmaxf(m, __shfl_xor_sync(0xffffffff, m, off, 8));
    float ex = (col < 6) ? expf(acc - m) : 0.f;
#pragma unroll
    for (int off = 4; off >= 1; off >>= 1)
        ex += __shfl_xor_sync(0xffffffff, ex, off, 8);
    float ls = m + logf(ex);
    if (active && col < 6)
        out[(size_t)node * 6 + col] = acc - ls;
}

// ---------------------------------------------------------------------------
static inline int cdiv(long long a, int b) { return (int)((a + b - 1) / b); }

extern "C" void kernel_launch(void* const* d_in, const int* in_sizes, int n_in,
                              void* d_out, int out_size) {
    const float* x  = (const float*)d_in[0];
    const void*  ei = d_in[1];
    const float* W1 = (const float*)d_in[2];
    const float* b1 = (const float*)d_in[3];
    const float* W2 = (const float*)d_in[4];
    const float* b2 = (const float*)d_in[5];
    const float* W3 = (const float*)d_in[6];
    const float* b3 = (const float*)d_in[7];
    float* out = (float*)d_out;

    int n = in_sizes[0] / 128;
    int e = in_sizes[1] / 2;

    __half *pHA, *pA16, *pH3;
    float  *pAgg;
    cudaGetSymbolAddress((void**)&pHA,  g_hA);
    cudaGetSymbolAddress((void**)&pAgg, g_aggB);
    cudaGetSymbolAddress((void**)&pA16, g_agg16);
    cudaGetSymbolAddress((void**)&pH3,  g_h3);

    const int T = 256;

    // ---- CSR build ----
    k_detect_zero<<<cdiv(n, T), T>>>(ei, e, n);
    k_convert_hist<<<cdiv(e, T), T>>>(ei, e);
    k_segments<<<cdiv(n, T), T>>>(n);
    k_permute<<<cdiv(e, T), T>>>(e);

    // ---- layer 1: x(128) -> 64 ----
    k_gemm64<128><<<cdiv((long long)n * 8, T), T>>>(x, W1, pHA, n);
    k_gather64<true, false><<<cdiv((long long)n * 8, T), T>>>(pHA, b1, pAgg, pA16, n);

    // ---- layer 2: 64 -> 64 ----
    k_gemm64<64><<<cdiv((long long)n * 8, T), T>>>(pAgg, W2, pHA, n);
    k_gather64<true, true><<<cdiv((long long)n * 8, T), T>>>(pHA, b2, pAgg, pA16, n);

    // ---- layer 3: 64 -> 6 (padded 8) + softmax ----
    k_gemm3<<<cdiv(n, 128), 128>>>(pA16, W3, pH3, n);
    k_gather3_softmax<<<cdiv((long long)n * 8, T), T>>>(pH3, b3, out, n);
}

// round 5
// speedup vs baseline: 1.9807x; 1.0095x over previous
#include <cuda_runtime.h>
#include <cuda_fp16.h>
#include <cstdint>
#include <math_constants.h>

// ---------------------------------------------------------------------------
// GCNNet: 3-layer GCN + log_softmax. CSR gather (atomic-free permute),
// fp16 rows, LDG.128 gathers, packed fp32x2 FMA, GEMM1 overlapped with CSR.
// ---------------------------------------------------------------------------

#define MAXN 100000
#define MAXE 3200000

__device__ float g_dinv[MAXN];
__device__ int   g_count[MAXN];
__device__ int   g_segstart[MAXN];
__device__ __align__(16) int2 g_sd[MAXE];     // (src, dst) packed
__device__ int   g_pos[MAXE];                 // slot within dst segment
__device__ __align__(16) float2 g_perm[MAXE]; // .x = src id bits, .y = norm
__device__ unsigned long long g_cursor0;
__device__ __align__(16) __half g_hA[(size_t)MAXN * 64];    // gemm out (gather src)
__device__ __align__(16) float  g_aggB[(size_t)MAXN * 64];  // gather out fp32
__device__ __align__(16) __half g_agg16[(size_t)MAXN * 64]; // gather out fp16
__device__ __align__(16) __half g_h3[(size_t)MAXN * 8];
__device__ int g_is64;

// packed fp32x2 FMA (Blackwell FFMA2)
__device__ __forceinline__ float2 fma2(float2 a, float2 b, float2 c) {
    float2 d;
    asm("{\n\t"
        ".reg .b64 ra, rb, rc, rd;\n\t"
        "mov.b64 ra, {%2, %3};\n\t"
        "mov.b64 rb, {%4, %5};\n\t"
        "mov.b64 rc, {%6, %7};\n\t"
        "fma.rn.f32x2 rd, ra, rb, rc;\n\t"
        "mov.b64 {%0, %1}, rd;\n\t"
        "}"
        : "=f"(d.x), "=f"(d.y)
        : "f"(a.x), "f"(a.y), "f"(b.x), "f"(b.y), "f"(c.x), "f"(c.y));
    return d;
}

// ---------------- setup ----------------
__global__ void k_detect_zero(const void* ei, int e, int n) {
    int i = blockIdx.x * blockDim.x + threadIdx.x;
    if (i < n) g_count[i] = 0;
    if (i == 0) g_cursor0 = 0ull;
    if (blockIdx.x == 0) {
        // int64 buffer: every 8-byte word is in [0, n). int32 buffer: 8-byte
        // view packs two ids (>= 2^32 unless the hi id happens to be 0).
        const long long* p = (const long long*)ei;
        int m = e < 1024 ? e : 1024;
        int bad = 0;
        for (int q = threadIdx.x; q < m; q += blockDim.x) {
            long long v = p[q];
            if (v < 0 || v >= (long long)n) bad = 1;
        }
        bad = __syncthreads_or(bad);
        if (threadIdx.x == 0) g_is64 = !bad;
    }
}

// histogram + record each edge's slot within its dst segment (atomic's return)
__global__ void k_hist(const void* ei, int e) {
    int i = blockIdx.x * blockDim.x + threadIdx.x;
    if (i >= e) return;
    int s, d;
    if (g_is64) {
        const long long* p = (const long long*)ei;
        s = (int)p[i];
        d = (int)p[e + i];
    } else {
        const int* p = (const int*)ei;
        s = p[i];
        d = p[e + i];
    }
    g_sd[i]  = make_int2(s, d);
    g_pos[i] = atomicAdd(&g_count[d], 1);
}

__global__ void k_segments(int n) {
    int i = blockIdx.x * blockDim.x + threadIdx.x;
    int lane = threadIdx.x & 31;
    int c = (i < n) ? g_count[i] : 0;
    int incl = c;
#pragma unroll
    for (int off = 1; off < 32; off <<= 1) {
        int v = __shfl_up_sync(0xffffffff, incl, off);
        if (lane >= off) incl += v;
    }
    int total = __shfl_sync(0xffffffff, incl, 31);
    unsigned long long base = 0;
    if (lane == 31) base = atomicAdd(&g_cursor0, (unsigned long long)total);
    base = __shfl_sync(0xffffffff, base, 31);
    if (i < n) {
        g_segstart[i] = (int)base + incl - c;
        g_dinv[i]     = rsqrtf((float)(c + 1));
    }
}

// atomic-free scatter into dst-grouped slots
__global__ void k_permute(int e) {
    int i = blockIdx.x * blockDim.x + threadIdx.x;
    if (i >= e) return;
    int2 sd = g_sd[i];
    int pos = g_pos[i];
    float nw = g_dinv[sd.x] * g_dinv[sd.y];
    g_perm[g_segstart[sd.y] + pos] = make_float2(__int_as_float(sd.x), nw);
}

// ---------------- GEMM: [n,K] fp32 @ [K,64] -> [n,64] fp16, f32x2 packed ----
template <int K>
__global__ void k_gemm64(const float* __restrict__ in, const float* __restrict__ W,
                         __half* __restrict__ out, int n) {
    __shared__ float2 Wp[(K / 2) * 64];   // Wp[j][c] = (W[2j][c], W[2j+1][c])
    for (int i = threadIdx.x; i < (K / 2) * 64; i += blockDim.x) {
        int j = i >> 6, cc = i & 63;
        Wp[i] = make_float2(W[(2 * j) * 64 + cc], W[(2 * j + 1) * 64 + cc]);
    }
    __syncthreads();

    int warp = (blockIdx.x * blockDim.x + threadIdx.x) >> 5;
    int lane = threadIdx.x & 31;
    int row0 = warp * 4;
    if (row0 >= n) return;
    int rows = n - row0; if (rows > 4) rows = 4;

    float2 acc[4][2] = {};
    for (int k = 0; k < K; k += 4) {
        int j = k >> 1;
        float4 xv[4];
#pragma unroll
        for (int r = 0; r < 4; r++)
            xv[r] = (r < rows) ? *(const float4*)(in + (size_t)(row0 + r) * K + k)
                               : make_float4(0.f, 0.f, 0.f, 0.f);
        float2 w00 = Wp[j * 64 + lane];
        float2 w01 = Wp[j * 64 + lane + 32];
        float2 w10 = Wp[(j + 1) * 64 + lane];
        float2 w11 = Wp[(j + 1) * 64 + lane + 32];
#pragma unroll
        for (int r = 0; r < 4; r++) {
            float2 a0 = make_float2(xv[r].x, xv[r].y);
            float2 a1 = make_float2(xv[r].z, xv[r].w);
            acc[r][0] = fma2(a0, w00, acc[r][0]);
            acc[r][1] = fma2(a0, w01, acc[r][1]);
            acc[r][0] = fma2(a1, w10, acc[r][0]);
            acc[r][1] = fma2(a1, w11, acc[r][1]);
        }
    }
#pragma unroll
    for (int r = 0; r < 4; r++) {
        if (r < rows) {
            out[(size_t)(row0 + r) * 64 + lane]      = __float2half(acc[r][0].x + acc[r][0].y);
            out[(size_t)(row0 + r) * 64 + lane + 32] = __float2half(acc[r][1].x + acc[r][1].y);
        }
    }
}

// ---------------- CSR gather: 8 lanes/node, LDG.128 rows, shuffled perm -----
template <bool RELU, bool OUT16>
__global__ void k_gather64(const __half* __restrict__ h, const float* __restrict__ b,
                           float* __restrict__ agg, __half* __restrict__ agg16, int n) {
    int tid = blockIdx.x * blockDim.x + threadIdx.x;
    int node = tid >> 3;
    int g = threadIdx.x & 7;
    bool active = (node < n);
    int nd = active ? node : (n - 1);
    int c = g * 8;   // 8 fp16 columns per lane

    float di = g_dinv[nd];
    float2 ww = make_float2(di * di, di * di);
    uint4 sr = *(const uint4*)(h + (size_t)nd * 64 + c);
    float4 b0 = *(const float4*)(b + c);
    float4 b1 = *(const float4*)(b + c + 4);
    float2 acc0 = fma2(__half22float2(*(half2*)&sr.x), ww, make_float2(b0.x, b0.y));
    float2 acc1 = fma2(__half22float2(*(half2*)&sr.y), ww, make_float2(b0.z, b0.w));
    float2 acc2 = fma2(__half22float2(*(half2*)&sr.z), ww, make_float2(b1.x, b1.y));
    float2 acc3 = fma2(__half22float2(*(half2*)&sr.w), ww, make_float2(b1.z, b1.w));

    int p   = active ? g_segstart[nd] : 0;
    int end = active ? (p + g_count[nd]) : 0;

    while (__any_sync(0xffffffffu, p < end)) {
        float2 ee = (p + g < end) ? g_perm[p + g] : make_float2(0.f, 0.f);
        int eis = __float_as_int(ee.x);
#pragma unroll
        for (int j = 0; j < 8; j++) {
            int   s  = __shfl_sync(0xffffffffu, eis, j, 8);
            float nw = __shfl_sync(0xffffffffu, ee.y, j, 8);
            if (p + j < end) {
                uint4 r = *(const uint4*)(h + (size_t)s * 64 + c);
                float2 nn = make_float2(nw, nw);
                acc0 = fma2(__half22float2(*(half2*)&r.x), nn, acc0);
                acc1 = fma2(__half22float2(*(half2*)&r.y), nn, acc1);
                acc2 = fma2(__half22float2(*(half2*)&r.z), nn, acc2);
                acc3 = fma2(__half22float2(*(half2*)&r.w), nn, acc3);
            }
        }
        p += 8;
    }
    if (!active) return;
    if (RELU) {
        acc0.x = fmaxf(acc0.x, 0.f); acc0.y = fmaxf(acc0.y, 0.f);
        acc1.x = fmaxf(acc1.x, 0.f); acc1.y = fmaxf(acc1.y, 0.f);
        acc2.x = fmaxf(acc2.x, 0.f); acc2.y = fmaxf(acc2.y, 0.f);
        acc3.x = fmaxf(acc3.x, 0.f); acc3.y = fmaxf(acc3.y, 0.f);
    }
    if (OUT16) {
        uint4 o;
        *(half2*)&o.x = __float22half2_rn(acc0);
        *(half2*)&o.y = __float22half2_rn(acc1);
        *(half2*)&o.z = __float22half2_rn(acc2);
        *(half2*)&o.w = __float22half2_rn(acc3);
        *(uint4*)(agg16 + (size_t)node * 64 + c) = o;
    } else {
        *(float4*)(agg + (size_t)node * 64 + c)     = make_float4(acc0.x, acc0.y, acc1.x, acc1.y);
        *(float4*)(agg + (size_t)node * 64 + c + 4) = make_float4(acc2.x, acc2.y, acc3.x, acc3.y);
    }
}

// ---------------- layer 3: [n,64] fp16 @ [64,6] -> [n,8] fp16 ----------------
__global__ void k_gemm3(const __half* __restrict__ in, const float* __restrict__ W,
                        __half* __restrict__ out, int n) {
    __shared__ float Ws[64 * 6];
    for (int i = threadIdx.x; i < 64 * 6; i += blockDim.x) Ws[i] = W[i];
    __syncthreads();
    int row = blockIdx.x * blockDim.x + threadIdx.x;
    if (row >= n) return;
    const uint4* xr = (const uint4*)(in + (size_t)row * 64);
    float acc[6] = {};
#pragma unroll
    for (int q = 0; q < 8; q++) {
        uint4 u = xr[q];
        float2 f0 = __half22float2(*(half2*)&u.x);
        float2 f1 = __half22float2(*(half2*)&u.y);
        float2 f2 = __half22float2(*(half2*)&u.z);
        float2 f3 = __half22float2(*(half2*)&u.w);
        float xs[8] = {f0.x, f0.y, f1.x, f1.y, f2.x, f2.y, f3.x, f3.y};
#pragma unroll
        for (int t = 0; t < 8; t++) {
            int k = q * 8 + t;
#pragma unroll
            for (int jj = 0; jj < 6; jj++)
                acc[jj] = fmaf(xs[t], Ws[k * 6 + jj], acc[jj]);
        }
    }
    __half* o = out + (size_t)row * 8;
#pragma unroll
    for (int jj = 0; jj < 6; jj++) o[jj] = __float2half(acc[jj]);
    o[6] = __float2half(0.f); o[7] = __float2half(0.f);
}

// ---------------- layer-3 gather (8 lanes/node) + fused log_softmax ---------
__global__ void k_gather3_softmax(const __half* __restrict__ h3, const float* __restrict__ b,
                                  float* __restrict__ out, int n) {
    int t = blockIdx.x * blockDim.x + threadIdx.x;
    int node = t >> 3;
    int col  = t & 7;
    bool active = (node < n);
    int nd = active ? node : 0;

    float di = g_dinv[nd];
    float w0 = di * di;
    float acc = __half2float(h3[(size_t)nd * 8 + col]);
    float bb  = (col < 6) ? b[col] : 0.f;
    acc = fmaf(acc, w0, bb);

    int p   = active ? g_segstart[nd] : 0;
    int end = active ? p + g_count[nd] : 0;
    for (; p < end; p++) {
        float2 ee = g_perm[p];
        acc = fmaf(__half2float(h3[(size_t)__float_as_int(ee.x) * 8 + col]), ee.y, acc);
    }

    float m = (col < 6) ? acc : -CUDART_INF_F;
#pragma unroll
    for (int off = 4; off >= 1; off >>= 1)
        m = fmaxf(m, __shfl_xor_sync(0xffffffff, m, off, 8));
    float ex = (col < 6) ? expf(acc - m) : 0.f;
#pragma unroll
    for (int off = 4; off >= 1; off >>= 1)
        ex += __shfl_xor_sync(0xffffffff, ex, off, 8);
    float ls = m + logf(ex);
    if (active && col < 6)
        out[(size_t)node * 6 + col] = acc - ls;
}

// ---------------------------------------------------------------------------
static inline int cdiv(long long a, int b) { return (int)((a + b - 1) / b); }

extern "C" void kernel_launch(void* const* d_in, const int* in_sizes, int n_in,
                              void* d_out, int out_size) {
    const float* x  = (const float*)d_in[0];
    const void*  ei = d_in[1];
    const float* W1 = (const float*)d_in[2];
    const float* b1 = (const float*)d_in[3];
    const float* W2 = (const float*)d_in[4];
    const float* b2 = (const float*)d_in[5];
    const float* W3 = (const float*)d_in[6];
    const float* b3 = (const float*)d_in[7];
    float* out = (float*)d_out;

    int n = in_sizes[0] / 128;
    int e = in_sizes[1] / 2;

    __half *pHA, *pA16, *pH3;
    float  *pAgg;
    cudaGetSymbolAddress((void**)&pHA,  g_hA);
    cudaGetSymbolAddress((void**)&pAgg, g_aggB);
    cudaGetSymbolAddress((void**)&pA16, g_agg16);
    cudaGetSymbolAddress((void**)&pH3,  g_h3);

    // side stream + events for overlapping GEMM1 with the CSR build
    // (created once; every call issues the identical launch sequence)
    static cudaStream_t s2 = nullptr;
    static cudaEvent_t ev_root = nullptr, ev_gemm = nullptr;
    if (!s2) {
        cudaStreamCreateWithFlags(&s2, cudaStreamNonBlocking);
        cudaEventCreateWithFlags(&ev_root, cudaEventDisableTiming);
        cudaEventCreateWithFlags(&ev_gemm, cudaEventDisableTiming);
    }

    const int T = 256;

    // fork: GEMM1 (independent of edge list) on side stream
    cudaEventRecord(ev_root, 0);
    cudaStreamWaitEvent(s2, ev_root, 0);
    k_gemm64<128><<<cdiv((long long)n * 8, T), T, 0, s2>>>(x, W1, pHA, n);
    cudaEventRecord(ev_gemm, s2);

    // ---- CSR build on main stream ----
    k_detect_zero<<<cdiv(n, T), T>>>(ei, e, n);
    k_hist<<<cdiv(e, T), T>>>(ei, e);
    k_segments<<<cdiv(n, T), T>>>(n);
    k_permute<<<cdiv(e, T), T>>>(e);

    // join: gather1 needs both CSR and GEMM1
    cudaStreamWaitEvent(0, ev_gemm, 0);

    // ---- layer 1 aggregation ----
    k_gather64<true, false><<<cdiv((long long)n * 8, T), T>>>(pHA, b1, pAgg, pA16, n);

    // ---- layer 2: 64 -> 64 ----
    k_gemm64<64><<<cdiv((long long)n * 8, T), T>>>(pAgg, W2, pHA, n);
    k_gather64<true, true><<<cdiv((long long)n * 8, T), T>>>(pHA, b2, pAgg, pA16, n);

    // ---- layer 3: 64 -> 6 (padded 8) + softmax ----
    k_gemm3<<<cdiv(n, 128), 128>>>(pA16, W3, pH3, n);
    k_gather3_softmax<<<cdiv((long long)n * 8, T), T>>>(pH3, b3, out, n);
}

// round 6
// speedup vs baseline: 1.9915x; 1.0054x over previous
#include <cuda_runtime.h>
#include <cuda_fp16.h>
#include <cstdint>
#include <math_constants.h>

// ---------------------------------------------------------------------------
// GCNNet: 3-layer GCN + log_softmax. CSR gather (atomic-free permute),
// fp16 rows, LDG.128 gathers, fp32x2 FMA, degree-sorted warp assignment,
// double-buffered perm loads, GEMM1 + degree-sort on side streams.
// ---------------------------------------------------------------------------

#define MAXN 100000
#define MAXE 3200000

__device__ float g_dinv[MAXN];
__device__ int   g_count[MAXN];
__device__ int   g_segstart[MAXN];
__device__ __align__(16) int2 g_sd[MAXE];     // (src, dst) packed
__device__ int   g_pos[MAXE];                 // slot within dst segment
__device__ __align__(16) float2 g_perm[MAXE]; // .x = src id bits, .y = norm
__device__ unsigned long long g_cursor0;
__device__ int   g_degbins[256];
__device__ int   g_bincur[256];
__device__ int   g_order[MAXN];               // nodes sorted by degree
__device__ __align__(16) __half g_hA[(size_t)MAXN * 64];
__device__ __align__(16) float  g_aggB[(size_t)MAXN * 64];
__device__ __align__(16) __half g_agg16[(size_t)MAXN * 64];
__device__ __align__(16) __half g_h3[(size_t)MAXN * 8];
__device__ int g_is64;

// packed fp32x2 FMA (Blackwell FFMA2)
__device__ __forceinline__ float2 fma2(float2 a, float2 b, float2 c) {
    float2 d;
    asm("{\n\t"
        ".reg .b64 ra, rb, rc, rd;\n\t"
        "mov.b64 ra, {%2, %3};\n\t"
        "mov.b64 rb, {%4, %5};\n\t"
        "mov.b64 rc, {%6, %7};\n\t"
        "fma.rn.f32x2 rd, ra, rb, rc;\n\t"
        "mov.b64 {%0, %1}, rd;\n\t"
        "}"
        : "=f"(d.x), "=f"(d.y)
        : "f"(a.x), "f"(a.y), "f"(b.x), "f"(b.y), "f"(c.x), "f"(c.y));
    return d;
}

// ---------------- setup ----------------
__global__ void k_detect_zero(const void* ei, int e, int n) {
    int i = blockIdx.x * blockDim.x + threadIdx.x;
    if (i < n) g_count[i] = 0;
    if (i < 256) g_degbins[i] = 0;
    if (i == 0) g_cursor0 = 0ull;
    if (blockIdx.x == 0) {
        // int64 buffer: every 8-byte word is in [0, n). int32 buffer: 8-byte
        // view packs two ids (>= 2^32 unless the hi id happens to be 0).
        const long long* p = (const long long*)ei;
        int m = e < 1024 ? e : 1024;
        int bad = 0;
        for (int q = threadIdx.x; q < m; q += blockDim.x) {
            long long v = p[q];
            if (v < 0 || v >= (long long)n) bad = 1;
        }
        bad = __syncthreads_or(bad);
        if (threadIdx.x == 0) g_is64 = !bad;
    }
}

// histogram + record each edge's slot within its dst segment (atomic's return)
__global__ void k_hist(const void* ei, int e) {
    int i = blockIdx.x * blockDim.x + threadIdx.x;
    if (i >= e) return;
    int s, d;
    if (g_is64) {
        const long long* p = (const long long*)ei;
        s = (int)p[i];
        d = (int)p[e + i];
    } else {
        const int* p = (const int*)ei;
        s = p[i];
        d = p[e + i];
    }
    g_sd[i]  = make_int2(s, d);
    g_pos[i] = atomicAdd(&g_count[d], 1);
}

__global__ void k_segments(int n) {
    int i = blockIdx.x * blockDim.x + threadIdx.x;
    int lane = threadIdx.x & 31;
    int c = (i < n) ? g_count[i] : 0;
    int incl = c;
#pragma unroll
    for (int off = 1; off < 32; off <<= 1) {
        int v = __shfl_up_sync(0xffffffff, incl, off);
        if (lane >= off) incl += v;
    }
    int total = __shfl_sync(0xffffffff, incl, 31);
    unsigned long long base = 0;
    if (lane == 31) base = atomicAdd(&g_cursor0, (unsigned long long)total);
    base = __shfl_sync(0xffffffff, base, 31);
    if (i < n) {
        g_segstart[i] = (int)base + incl - c;
        g_dinv[i]     = rsqrtf((float)(c + 1));
    }
}

// atomic-free scatter into dst-grouped slots
__global__ void k_permute(int e) {
    int i = blockIdx.x * blockDim.x + threadIdx.x;
    if (i >= e) return;
    int2 sd = g_sd[i];
    int pos = g_pos[i];
    float nw = g_dinv[sd.x] * g_dinv[sd.y];
    g_perm[g_segstart[sd.y] + pos] = make_float2(__int_as_float(sd.x), nw);
}

// ---------------- degree sort (counting sort into 256 bins) ----------------
__device__ __forceinline__ int warp_agg_add(int* addr, int key) {
    // warp-aggregated atomicAdd for lanes sharing `key`'s address; returns rank base+rank
    unsigned mask = __match_any_sync(0xffffffffu, key);
    int lane = threadIdx.x & 31;
    int leader = __ffs(mask) - 1;
    int rank = __popc(mask & ((1u << lane) - 1));
    int base = 0;
    if (lane == leader) base = atomicAdd(addr, __popc(mask));
    base = __shfl_sync(0xffffffffu, base, leader);
    return base + rank;
}

__global__ void k_deghist(int n) {
    int i = blockIdx.x * blockDim.x + threadIdx.x;
    if (i >= n) return;
    int bin = min(g_count[i], 255);
    warp_agg_add(&g_degbins[bin], bin);
}

__global__ void k_degscan() {
    __shared__ int sa[256], sb[256];
    int t = threadIdx.x;
    sa[t] = g_degbins[t];
    __syncthreads();
    int* src = sa; int* dst = sb;
    for (int off = 1; off < 256; off <<= 1) {
        int v = src[t] + ((t >= off) ? src[t - off] : 0);
        dst[t] = v;
        __syncthreads();
        int* tmp = src; src = dst; dst = tmp;
        __syncthreads();
    }
    // src holds inclusive scan
    g_bincur[t] = src[t] - g_degbins[t];   // exclusive start
}

__global__ void k_degscatter(int n) {
    int i = blockIdx.x * blockDim.x + threadIdx.x;
    if (i >= n) return;
    int bin = min(g_count[i], 255);
    int pos = warp_agg_add(&g_bincur[bin], bin);
    g_order[pos] = i;
}

// ---------------- GEMM: [n,K] fp32 @ [K,64] -> [n,64] fp16, f32x2 packed ----
template <int K>
__global__ void k_gemm64(const float* __restrict__ in, const float* __restrict__ W,
                         __half* __restrict__ out, int n) {
    __shared__ float2 Wp[(K / 2) * 64];   // Wp[j][c] = (W[2j][c], W[2j+1][c])
    for (int i = threadIdx.x; i < (K / 2) * 64; i += blockDim.x) {
        int j = i >> 6, cc = i & 63;
        Wp[i] = make_float2(W[(2 * j) * 64 + cc], W[(2 * j + 1) * 64 + cc]);
    }
    __syncthreads();

    int warp = (blockIdx.x * blockDim.x + threadIdx.x) >> 5;
    int lane = threadIdx.x & 31;
    int row0 = warp * 4;
    if (row0 >= n) return;
    int rows = n - row0; if (rows > 4) rows = 4;

    float2 acc[4][2] = {};
    for (int k = 0; k < K; k += 4) {
        int j = k >> 1;
        float4 xv[4];
#pragma unroll
        for (int r = 0; r < 4; r++)
            xv[r] = (r < rows) ? *(const float4*)(in + (size_t)(row0 + r) * K + k)
                               : make_float4(0.f, 0.f, 0.f, 0.f);
        float2 w00 = Wp[j * 64 + lane];
        float2 w01 = Wp[j * 64 + lane + 32];
        float2 w10 = Wp[(j + 1) * 64 + lane];
        float2 w11 = Wp[(j + 1) * 64 + lane + 32];
#pragma unroll
        for (int r = 0; r < 4; r++) {
            float2 a0 = make_float2(xv[r].x, xv[r].y);
            float2 a1 = make_float2(xv[r].z, xv[r].w);
            acc[r][0] = fma2(a0, w00, acc[r][0]);
            acc[r][1] = fma2(a0, w01, acc[r][1]);
            acc[r][0] = fma2(a1, w10, acc[r][0]);
            acc[r][1] = fma2(a1, w11, acc[r][1]);
        }
    }
#pragma unroll
    for (int r = 0; r < 4; r++) {
        if (r < rows) {
            out[(size_t)(row0 + r) * 64 + lane]      = __float2half(acc[r][0].x + acc[r][0].y);
            out[(size_t)(row0 + r) * 64 + lane + 32] = __float2half(acc[r][1].x + acc[r][1].y);
        }
    }
}

// ---------------- CSR gather: 8 lanes/node, order[], double-buffered perm ---
template <bool RELU, bool OUT16>
__global__ void k_gather64(const __half* __restrict__ h, const float* __restrict__ b,
                           float* __restrict__ agg, __half* __restrict__ agg16, int n) {
    int tid = blockIdx.x * blockDim.x + threadIdx.x;
    int idx = tid >> 3;
    int g = threadIdx.x & 7;
    bool active = (idx < n);
    int node = g_order[active ? idx : 0];

    int c = g * 8;   // 8 fp16 columns per lane
    float di = g_dinv[node];
    float2 ww = make_float2(di * di, di * di);
    uint4 sr = *(const uint4*)(h + (size_t)node * 64 + c);
    float4 b0 = *(const float4*)(b + c);
    float4 b1 = *(const float4*)(b + c + 4);
    float2 acc0 = fma2(__half22float2(*(half2*)&sr.x), ww, make_float2(b0.x, b0.y));
    float2 acc1 = fma2(__half22float2(*(half2*)&sr.y), ww, make_float2(b0.z, b0.w));
    float2 acc2 = fma2(__half22float2(*(half2*)&sr.z), ww, make_float2(b1.x, b1.y));
    float2 acc3 = fma2(__half22float2(*(half2*)&sr.w), ww, make_float2(b1.z, b1.w));

    int p   = active ? g_segstart[node] : 0;
    int end = active ? (p + g_count[node]) : 0;

    // double-buffered perm batches of 8 edges per node-group
    float2 ee = (p + g < end) ? g_perm[p + g] : make_float2(0.f, 0.f);
    while (__any_sync(0xffffffffu, p < end)) {
        float2 cur = ee;
        int pn = p + 8;
        ee = (pn + g < end) ? g_perm[pn + g] : make_float2(0.f, 0.f);
        int eis = __float_as_int(cur.x);
#pragma unroll
        for (int j = 0; j < 8; j++) {
            int   s  = __shfl_sync(0xffffffffu, eis, j, 8);
            float nw = __shfl_sync(0xffffffffu, cur.y, j, 8);
            if (p + j < end) {
                uint4 r = *(const uint4*)(h + (size_t)s * 64 + c);
                float2 nn = make_float2(nw, nw);
                acc0 = fma2(__half22float2(*(half2*)&r.x), nn, acc0);
                acc1 = fma2(__half22float2(*(half2*)&r.y), nn, acc1);
                acc2 = fma2(__half22float2(*(half2*)&r.z), nn, acc2);
                acc3 = fma2(__half22float2(*(half2*)&r.w), nn, acc3);
            }
        }
        p = pn;
    }
    if (!active) return;
    if (RELU) {
        acc0.x = fmaxf(acc0.x, 0.f); acc0.y = fmaxf(acc0.y, 0.f);
        acc1.x = fmaxf(acc1.x, 0.f); acc1.y = fmaxf(acc1.y, 0.f);
        acc2.x = fmaxf(acc2.x, 0.f); acc2.y = fmaxf(acc2.y, 0.f);
        acc3.x = fmaxf(acc3.x, 0.f); acc3.y = fmaxf(acc3.y, 0.f);
    }
    if (OUT16) {
        uint4 o;
        *(half2*)&o.x = __float22half2_rn(acc0);
        *(half2*)&o.y = __float22half2_rn(acc1);
        *(half2*)&o.z = __float22half2_rn(acc2);
        *(half2*)&o.w = __float22half2_rn(acc3);
        *(uint4*)(agg16 + (size_t)node * 64 + c) = o;
    } else {
        *(float4*)(agg + (size_t)node * 64 + c)     = make_float4(acc0.x, acc0.y, acc1.x, acc1.y);
        *(float4*)(agg + (size_t)node * 64 + c + 4) = make_float4(acc2.x, acc2.y, acc3.x, acc3.y);
    }
}

// ---------------- layer 3: [n,64] fp16 @ [64,6] -> [n,8] fp16 ----------------
__global__ void k_gemm3(const __half* __restrict__ in, const float* __restrict__ W,
                        __half* __restrict__ out, int n) {
    __shared__ float Ws[64 * 6];
    for (int i = threadIdx.x; i < 64 * 6; i += blockDim.x) Ws[i] = W[i];
    __syncthreads();
    int row = blockIdx.x * blockDim.x + threadIdx.x;
    if (row >= n) return;
    const uint4* xr = (const uint4*)(in + (size_t)row * 64);
    float acc[6] = {};
#pragma unroll
    for (int q = 0; q < 8; q++) {
        uint4 u = xr[q];
        float2 f0 = __half22float2(*(half2*)&u.x);
        float2 f1 = __half22float2(*(half2*)&u.y);
        float2 f2 = __half22float2(*(half2*)&u.z);
        float2 f3 = __half22float2(*(half2*)&u.w);
        float xs[8] = {f0.x, f0.y, f1.x, f1.y, f2.x, f2.y, f3.x, f3.y};
#pragma unroll
        for (int t = 0; t < 8; t++) {
            int k = q * 8 + t;
#pragma unroll
            for (int jj = 0; jj < 6; jj++)
                acc[jj] = fmaf(xs[t], Ws[k * 6 + jj], acc[jj]);
        }
    }
    __half* o = out + (size_t)row * 8;
#pragma unroll
    for (int jj = 0; jj < 6; jj++) o[jj] = __float2half(acc[jj]);
    o[6] = __float2half(0.f); o[7] = __float2half(0.f);
}

// ---------------- layer-3 gather (8 lanes/node) + fused log_softmax ---------
__global__ void k_gather3_softmax(const __half* __restrict__ h3, const float* __restrict__ b,
                                  float* __restrict__ out, int n) {
    int t = blockIdx.x * blockDim.x + threadIdx.x;
    int idx = t >> 3;
    int col = t & 7;
    bool active = (idx < n);
    int nd = g_order[active ? idx : 0];

    float di = g_dinv[nd];
    float w0 = di * di;
    float acc = __half2float(h3[(size_t)nd * 8 + col]);
    float bb  = (col < 6) ? b[col] : 0.f;
    acc = fmaf(acc, w0, bb);

    int p   = active ? g_segstart[nd] : 0;
    int end = active ? p + g_count[nd] : 0;
    for (; p < end; p++) {
        float2 ee = g_perm[p];
        acc = fmaf(__half2float(h3[(size_t)__float_as_int(ee.x) * 8 + col]), ee.y, acc);
    }

    float m = (col < 6) ? acc : -CUDART_INF_F;
#pragma unroll
    for (int off = 4; off >= 1; off >>= 1)
        m = fmaxf(m, __shfl_xor_sync(0xffffffff, m, off, 8));
    float ex = (col < 6) ? expf(acc - m) : 0.f;
#pragma unroll
    for (int off = 4; off >= 1; off >>= 1)
        ex += __shfl_xor_sync(0xffffffff, ex, off, 8);
    float ls = m + logf(ex);
    if (active && col < 6)
        out[(size_t)nd * 6 + col] = acc - ls;
}

// ---------------------------------------------------------------------------
static inline int cdiv(long long a, int b) { return (int)((a + b - 1) / b); }

extern "C" void kernel_launch(void* const* d_in, const int* in_sizes, int n_in,
                              void* d_out, int out_size) {
    const float* x  = (const float*)d_in[0];
    const void*  ei = d_in[1];
    const float* W1 = (const float*)d_in[2];
    const float* b1 = (const float*)d_in[3];
    const float* W2 = (const float*)d_in[4];
    const float* b2 = (const float*)d_in[5];
    const float* W3 = (const float*)d_in[6];
    const float* b3 = (const float*)d_in[7];
    float* out = (float*)d_out;

    int n = in_sizes[0] / 128;
    int e = in_sizes[1] / 2;

    __half *pHA, *pA16, *pH3;
    float  *pAgg;
    cudaGetSymbolAddress((void**)&pHA,  g_hA);
    cudaGetSymbolAddress((void**)&pAgg, g_aggB);
    cudaGetSymbolAddress((void**)&pA16, g_agg16);
    cudaGetSymbolAddress((void**)&pH3,  g_h3);

    static cudaStream_t s2 = nullptr, s3 = nullptr;
    static cudaEvent_t ev_root = nullptr, ev_gemm = nullptr, ev_hist = nullptr, ev_order = nullptr;
    if (!s2) {
        cudaStreamCreateWithFlags(&s2, cudaStreamNonBlocking);
        cudaStreamCreateWithFlags(&s3, cudaStreamNonBlocking);
        cudaEventCreateWithFlags(&ev_root,  cudaEventDisableTiming);
        cudaEventCreateWithFlags(&ev_gemm,  cudaEventDisableTiming);
        cudaEventCreateWithFlags(&ev_hist,  cudaEventDisableTiming);
        cudaEventCreateWithFlags(&ev_order, cudaEventDisableTiming);
    }

    const int T = 256;

    // fork: GEMM1 (independent of edge list) on side stream
    cudaEventRecord(ev_root, 0);
    cudaStreamWaitEvent(s2, ev_root, 0);
    k_gemm64<128><<<cdiv((long long)n * 8, T), T, 0, s2>>>(x, W1, pHA, n);
    cudaEventRecord(ev_gemm, s2);

    // ---- CSR build on main stream ----
    k_detect_zero<<<cdiv(n, T), T>>>(ei, e, n);
    k_hist<<<cdiv(e, T), T>>>(ei, e);
    cudaEventRecord(ev_hist, 0);

    // fork: degree sort on s3 (depends only on g_count)
    cudaStreamWaitEvent(s3, ev_hist, 0);
    k_deghist<<<cdiv(n, T), T, 0, s3>>>(n);
    k_degscan<<<1, 256, 0, s3>>>();
    k_degscatter<<<cdiv(n, T), T, 0, s3>>>(n);
    cudaEventRecord(ev_order, s3);

    k_segments<<<cdiv(n, T), T>>>(n);
    k_permute<<<cdiv(e, T), T>>>(e);

    // join: gather1 needs CSR + GEMM1 + order
    cudaStreamWaitEvent(0, ev_gemm, 0);
    cudaStreamWaitEvent(0, ev_order, 0);

    // ---- layer 1 aggregation ----
    k_gather64<true, false><<<cdiv((long long)n * 8, T), T>>>(pHA, b1, pAgg, pA16, n);

    // ---- layer 2: 64 -> 64 ----
    k_gemm64<64><<<cdiv((long long)n * 8, T), T>>>(pAgg, W2, pHA, n);
    k_gather64<true, true><<<cdiv((long long)n * 8, T), T>>>(pHA, b2, pAgg, pA16, n);

    // ---- layer 3: 64 -> 6 (padded 8) + softmax ----
    k_gemm3<<<cdiv(n, 128), 128>>>(pA16, W3, pH3, n);
    k_gather3_softmax<<<cdiv((long long)n * 8, T), T>>>(pH3, b3, out, n);
}